// round 14
// baseline (speedup 1.0000x reference)
#include <cuda_runtime.h>
#include <cuda.h>
#include <cuda_bf16.h>
#include <math.h>
#include <stdint.h>

#define NN 10000
#define EE 320000
#define PI_F 3.14159265358979323846f
#define CDIV(a,b) (((a)+(b)-1)/(b))

// GEMM config: 3-stage TMA pipeline, 128x128 CTA tile, K-chunk 64 (bf16)
#define GK_NIT 157
#define NSTG 3
#define STG_BYTES 65536
#define OFF_AH 0
#define OFF_AL 16384
#define OFF_BH 32768
#define OFF_BL 49152
#define SM_MB  196608
#define SMEM_SZ 196672

// ---------------- scratch ----------------
__device__ __nv_bfloat16 g_Vhi [100000000];
__device__ __nv_bfloat16 g_Vlo [100000000];
__device__ __nv_bfloat16 g_VThi[100000000];
__device__ __nv_bfloat16 g_VTlo[100000000];
__device__ __nv_bfloat16 g_hTh [128*NN],  g_hTl [128*NN];
__device__ __nv_bfloat16 g_S1Th[384*NN],  g_S1Tl[384*NN];
__device__ __nv_bfloat16 g_X2Th[256*NN],  g_X2Tl[256*NN];
__device__ __nv_bfloat16 g_S2Th[768*NN],  g_S2Tl[768*NN];
__device__ __nv_bfloat16 g_X3Th[512*NN],  g_X3Tl[512*NN];
__device__ __nv_bfloat16 g_S3Th[512*NN],  g_S3Tl[512*NN];

__device__ float g_h [NN*128];
__device__ float g_C1[NN*128];
__device__ float g_Y [NN*384];
__device__ float g_C2[NN*256];
__device__ float g_Z [NN*768];
__device__ float g_C3[NN*512];
__device__ float g_Wo[NN*512];
__device__ float g_rep[NN*896];
__device__ float g_agg[NN*896];
__device__ float g_filt[3*NN];
__device__ int   g_src[EE];
__device__ int   g_dst[EE];
__device__ int   g_is64;
__device__ int   g_deg[NN];
__device__ int   g_off[NN+1];
__device__ int   g_cur[NN];
__device__ int   g_esrc[EE];
__device__ float g_hgat[NN*32];
__device__ float g_asrc[NN*2];
__device__ float g_adst[NN*2];
__device__ float g_gatout[NN*32];
__device__ float g_gv[NN*16];
__device__ float g_o2[NN*16];

// ---------------- PTX helpers (base-target features only) ----------------
__device__ __forceinline__ uint32_t su32(const void* p) {
    uint32_t a;
    asm("{ .reg .u64 t; cvta.to.shared.u64 t, %1; cvt.u32.u64 %0, t; }" : "=r"(a) : "l"(p));
    return a;
}
#define MBAR_INIT(a, cnt) \
    asm volatile("mbarrier.init.shared.b64 [%0], %1;" :: "r"(a), "r"((uint32_t)(cnt)) : "memory")
#define MBAR_EXPECT_TX(a, b) \
    asm volatile("mbarrier.arrive.expect_tx.shared.b64 _, [%0], %1;" :: "r"(a), "r"((uint32_t)(b)) : "memory")
#define MBAR_WAIT(a, ph) do { \
    uint32_t _m = (a); uint32_t _p = (ph); uint32_t _d; \
    asm volatile("{\n\t.reg .pred p;\n\t" \
        "mbarrier.try_wait.parity.shared.b64 p, [%1], %2;\n\t" \
        "selp.b32 %0, 1, 0, p;\n\t}" : "=r"(_d) : "r"(_m), "r"(_p) : "memory"); \
    if (!_d) { \
        asm volatile("{\n\t.reg .pred P1;\n\t" \
            "WL_%=:\n\t" \
            "mbarrier.try_wait.parity.shared.b64 P1, [%0], %1;\n\t" \
            "@P1 bra.uni WD_%=;\n\t" \
            "bra.uni WL_%=;\n\t" \
            "WD_%=:\n\t}" :: "r"(_m), "r"(_p) : "memory"); \
    } } while (0)

__device__ __forceinline__ void tma2d(uint32_t sa, const CUtensorMap* tm, int x, int y, uint32_t mb) {
    asm volatile(
        "cp.async.bulk.tensor.2d.shared::cta.global.tile.mbarrier::complete_tx::bytes "
        "[%0], [%1, {%2, %3}], [%4];"
        :: "r"(sa), "l"(tm), "r"(x), "r"(y), "r"(mb) : "memory");
}
__device__ __forceinline__ void ldm_x4(uint32_t* r, uint32_t addr) {
    asm volatile("ldmatrix.sync.aligned.m8n8.x4.shared.b16 {%0,%1,%2,%3}, [%4];"
        : "=r"(r[0]), "=r"(r[1]), "=r"(r[2]), "=r"(r[3]) : "r"(addr));
}
__device__ __forceinline__ void mma16816(float* d, const uint32_t* a, uint32_t b0, uint32_t b1) {
    asm volatile("mma.sync.aligned.m16n8k16.row.col.f32.bf16.bf16.f32 "
        "{%0,%1,%2,%3}, {%4,%5,%6,%7}, {%8,%9}, {%0,%1,%2,%3};"
        : "+f"(d[0]), "+f"(d[1]), "+f"(d[2]), "+f"(d[3])
        : "r"(a[0]), "r"(a[1]), "r"(a[2]), "r"(a[3]), "r"(b0), "r"(b1));
}
#define SWZ(o) ((o) ^ (((o) >> 3) & 0x70))

// ---------------- HMMA GEMM: C[10000,NC] = A(row-major,K=10000) @ B([NC][K] k-major)^T ----------------
// grid.x = bn tiles (fast dim => co-scheduled CTAs share the same A row-panel in L2),
// grid.y = bm tiles.
__global__ void __launch_bounds__(256, 1) gemm_mma(
    const __grid_constant__ CUtensorMap tmAh,
    const __grid_constant__ CUtensorMap tmAl,
    const __grid_constant__ CUtensorMap tmBh,
    const __grid_constant__ CUtensorMap tmBl,
    float* __restrict__ C, int NC)
{
    extern __shared__ char smem[];
    const uint32_t sb = su32(smem);
    const int tid = threadIdx.x, wid = tid >> 5, lane = tid & 31;
    const int bn = blockIdx.x * 128;
    const int bm = blockIdx.y * 128;
    const int warp_m = (wid & 3) * 32;
    const int warp_n = (wid >> 2) * 64;
    const int lrow  = lane & 15;
    const int lcolb = (lane >> 4) << 4;

    if (tid == 0) {
        #pragma unroll
        for (int s = 0; s < NSTG; s++) MBAR_INIT(sb + SM_MB + s*8, 1);
        asm volatile("fence.proxy.async.shared::cta;" ::: "memory");
    }
    __syncthreads();

    if (tid == 0) {
        #pragma unroll
        for (int p = 0; p < NSTG; p++) {
            uint32_t base = sb + p * STG_BYTES;
            MBAR_EXPECT_TX(sb + SM_MB + p*8, STG_BYTES);
            tma2d(base + OFF_AH, &tmAh, p*64, bm, sb + SM_MB + p*8);
            tma2d(base + OFF_AL, &tmAl, p*64, bm, sb + SM_MB + p*8);
            tma2d(base + OFF_BH, &tmBh, p*64, bn, sb + SM_MB + p*8);
            tma2d(base + OFF_BL, &tmBl, p*64, bn, sb + SM_MB + p*8);
        }
    }

    float acc[2][8][4];
    #pragma unroll
    for (int mt = 0; mt < 2; mt++)
        #pragma unroll
        for (int nt = 0; nt < 8; nt++)
            #pragma unroll
            for (int r = 0; r < 4; r++) acc[mt][nt][r] = 0.f;

    int b = 0;
    for (int it = 0; it < GK_NIT; it++) {
        MBAR_WAIT(sb + SM_MB + b*8, (it / NSTG) & 1);
        const uint32_t base = sb + b * STG_BYTES;
        #pragma unroll
        for (int k16 = 0; k16 < 4; k16++) {
            const int kb = k16 * 32;
            uint32_t ah[2][4], al[2][4], bh[4][4], bl[4][4];
            #pragma unroll
            for (int mt = 0; mt < 2; mt++) {
                uint32_t sw = SWZ((uint32_t)((warp_m + mt*16 + lrow) * 128 + kb + lcolb));
                ldm_x4(ah[mt], base + OFF_AH + sw);
                ldm_x4(al[mt], base + OFF_AL + sw);
            }
            #pragma unroll
            for (int j = 0; j < 4; j++) {
                uint32_t sw = SWZ((uint32_t)((warp_n + j*16 + lrow) * 128 + kb + lcolb));
                ldm_x4(bh[j], base + OFF_BH + sw);
                ldm_x4(bl[j], base + OFF_BL + sw);
            }
            // term-major issue: 16 independent accumulators between reuses
            #pragma unroll
            for (int j = 0; j < 4; j++)
                #pragma unroll
                for (int mt = 0; mt < 2; mt++) {
                    mma16816(acc[mt][2*j],   ah[mt], bh[j][0], bh[j][2]);
                    mma16816(acc[mt][2*j+1], ah[mt], bh[j][1], bh[j][3]);
                }
            #pragma unroll
            for (int j = 0; j < 4; j++)
                #pragma unroll
                for (int mt = 0; mt < 2; mt++) {
                    mma16816(acc[mt][2*j],   ah[mt], bl[j][0], bl[j][2]);
                    mma16816(acc[mt][2*j+1], ah[mt], bl[j][1], bl[j][3]);
                }
            #pragma unroll
            for (int j = 0; j < 4; j++)
                #pragma unroll
                for (int mt = 0; mt < 2; mt++) {
                    mma16816(acc[mt][2*j],   al[mt], bh[j][0], bh[j][2]);
                    mma16816(acc[mt][2*j+1], al[mt], bh[j][1], bh[j][3]);
                }
        }
        __syncthreads();
        if (tid == 0 && it + NSTG < GK_NIT) {
            MBAR_EXPECT_TX(sb + SM_MB + b*8, STG_BYTES);
            const int k0 = (it + NSTG) * 64;
            tma2d(base + OFF_AH, &tmAh, k0, bm, sb + SM_MB + b*8);
            tma2d(base + OFF_AL, &tmAl, k0, bm, sb + SM_MB + b*8);
            tma2d(base + OFF_BH, &tmBh, k0, bn, sb + SM_MB + b*8);
            tma2d(base + OFF_BL, &tmBl, k0, bn, sb + SM_MB + b*8);
        }
        b = (b + 1 == NSTG) ? 0 : b + 1;
    }

    // epilogue
    #pragma unroll
    for (int mt = 0; mt < 2; mt++) {
        #pragma unroll
        for (int nt = 0; nt < 8; nt++) {
            int row0 = bm + warp_m + mt*16 + (lane >> 2);
            int col  = bn + warp_n + nt*8 + (lane & 3)*2;
            if (row0 < NN) {
                float2 v; v.x = acc[mt][nt][0]; v.y = acc[mt][nt][1];
                *(float2*)&C[(size_t)row0 * NC + col] = v;
            }
            if (row0 + 8 < NN) {
                float2 v; v.x = acc[mt][nt][2]; v.y = acc[mt][nt][3];
                *(float2*)&C[(size_t)(row0 + 8) * NC + col] = v;
            }
        }
    }
}

// ---------------- prep: fused split + transpose-split of V (read V once) ----------------
__global__ void k_splitAll(const float* __restrict__ V) {
    __shared__ float t[32][33];
    int i0 = blockIdx.x*32, j0 = blockIdx.y*32;
    int x = threadIdx.x, y0 = threadIdx.y;
    #pragma unroll
    for (int yy = 0; yy < 32; yy += 8) {
        int i = i0 + y0 + yy, j = j0 + x;
        float v = 0.f;
        if (i < NN && j < NN) {
            v = V[(size_t)i*NN + j];
            __nv_bfloat16 h = __float2bfloat16(v);
            g_Vhi[(size_t)i*NN + j] = h;
            g_Vlo[(size_t)i*NN + j] = __float2bfloat16(v - __bfloat162float(h));
        }
        t[y0+yy][x] = v;
    }
    __syncthreads();
    #pragma unroll
    for (int yy = 0; yy < 32; yy += 8) {
        int j = j0 + y0 + yy, i = i0 + x;
        if (j < NN && i < NN) {
            float v = t[x][y0+yy];
            __nv_bfloat16 h = __float2bfloat16(v);
            g_VThi[(size_t)j*NN + i] = h;
            g_VTlo[(size_t)j*NN + i] = __float2bfloat16(v - __bfloat162float(h));
        }
    }
}

// MODE 0: copy, 1: abs, 2: scale by filt[filtIdx], 3: Z col remap + abs
template<int MODE>
__global__ void k_tsplit(const float* __restrict__ src, int srcW, int col0,
                         __nv_bfloat16* __restrict__ oh, __nv_bfloat16* __restrict__ ol,
                         int outRows, int filtIdx)
{
    __shared__ float t[32][33];
    int i0 = blockIdx.x*32;
    int j0 = blockIdx.y*32;
    int x = threadIdx.x, y0 = threadIdx.y;
    #pragma unroll
    for (int yy = 0; yy < 32; yy += 8) {
        int i = i0 + y0 + yy, j = j0 + x;
        float v = 0.f;
        if (i < NN && j < outRows) {
            int c;
            if (MODE == 3) { const int zo[4] = {256,512,384,640}; c = zo[j>>7] + (j&127); }
            else c = col0 + j;
            v = src[(size_t)i*srcW + c];
            if (MODE == 1 || MODE == 3) v = fabsf(v);
            if (MODE == 2) v *= g_filt[filtIdx*NN + i];
        }
        t[y0+yy][x] = v;
    }
    __syncthreads();
    #pragma unroll
    for (int yy = 0; yy < 32; yy += 8) {
        int j = j0 + y0 + yy, i = i0 + x;
        if (j < outRows && i < NN) {
            float v = t[x][y0+yy];
            __nv_bfloat16 h = __float2bfloat16(v);
            oh[(size_t)j*NN + i] = h;
            ol[(size_t)j*NN + i] = __float2bfloat16(v - __bfloat162float(h));
        }
    }
}

// ---------------- front-end / edges / graph stages ----------------
__global__ void k_detect(const unsigned int* __restrict__ w) {
    __shared__ unsigned acc_s;
    if (threadIdx.x == 0) acc_s = 0u;
    __syncthreads();
    unsigned a = 0u;
    for (int i = threadIdx.x; i < 4096; i += blockDim.x) a |= w[2*i + 1];
    atomicOr(&acc_s, a);
    __syncthreads();
    if (threadIdx.x == 0) g_is64 = (acc_s == 0u) ? 1 : 0;
}

__global__ void k_conv(const void* __restrict__ ei) {
    int e = blockIdx.x*256 + threadIdx.x;
    if (e >= EE) return;
    if (g_is64) {
        const long long* p = (const long long*)ei;
        g_src[e] = (int)p[e];  g_dst[e] = (int)p[EE + e];
    } else {
        const int* p = (const int*)ei;
        g_src[e] = p[e];  g_dst[e] = p[EE + e];
    }
}

__global__ void k_filters(const float* __restrict__ lamb) {
    int i = blockIdx.x*256 + threadIdx.x;
    if (i >= NN) return;
    float lam = lamb[i];
    float l0 = 8.f*lam; if (l0 == 0.f) l0 = 1e-7f;
    float y0 = 2.f*PI_F*l0;
    g_filt[i] = sinf(y0)/y0;
    float l1 = lam*0.25f; if (l1 == 0.f) l1 = 1e-8f;
    g_filt[NN+i]   = sinf(l1)/(PI_F*l1)*(1.f-cosf(l1));
    float l2 = lam*0.5f;  if (l2 == 0.f) l2 = 1e-8f;
    g_filt[2*NN+i] = sinf(l2)/(PI_F*l2)*(1.f-cosf(l2));
}

__global__ void k_xw1(const float* __restrict__ x, const float* __restrict__ W1, const float* __restrict__ b1) {
    __shared__ float xr[8][128];
    int n0 = blockIdx.x * 8;
    int c = threadIdx.x;
#pragma unroll
    for (int i = 0; i < 8; i++) xr[i][c] = x[(size_t)(n0+i)*128 + c];
    __syncthreads();
    float acc[8];
#pragma unroll
    for (int i = 0; i < 8; i++) acc[i] = b1[c];
    for (int k = 0; k < 128; k++) {
        float w = W1[k*128 + c];
#pragma unroll
        for (int i = 0; i < 8; i++) acc[i] += xr[i][k]*w;
    }
#pragma unroll
    for (int i = 0; i < 8; i++) g_h[(size_t)(n0+i)*128 + c] = acc[i];
}

__global__ void k_rep() {
    int i = blockIdx.x;
    for (int j = threadIdx.x; j < 896; j += blockDim.x) {
        float v;
        if (j < 128)      v = g_Y[(size_t)i*384 + j];
        else if (j < 384) v = g_Z[(size_t)i*768 + (j-128)];
        else              v = g_Wo[(size_t)i*512 + (j-384)];
        g_rep[(size_t)i*896 + j] = v;
    }
}

__global__ void k_deg() {
    int e = blockIdx.x*256 + threadIdx.x;
    if (e < EE) atomicAdd(&g_deg[g_dst[e]], 1);
}

__global__ void k_scan() {
    __shared__ int sh[1024];
    __shared__ int carry;
    int tid = threadIdx.x;
    if (tid == 0) carry = 0;
    __syncthreads();
    for (int base = 0; base < NN; base += 1024) {
        int idx = base + tid;
        int v = (idx < NN) ? g_deg[idx] : 0;
        sh[tid] = v;
        __syncthreads();
        for (int o = 1; o < 1024; o <<= 1) {
            int t = (tid >= o) ? sh[tid-o] : 0;
            __syncthreads();
            sh[tid] += t;
            __syncthreads();
        }
        if (idx < NN) g_off[idx] = carry + sh[tid] - v;
        __syncthreads();
        if (tid == 0) carry += sh[1023];
        __syncthreads();
    }
    if (tid == 0) g_off[NN] = carry;
}

__global__ void k_scatter() {
    int e = blockIdx.x*256 + threadIdx.x;
    if (e < EE) {
        int d = g_dst[e];
        int pos = atomicAdd(&g_cur[d], 1);
        g_esrc[pos] = g_src[e];
    }
}

__global__ void __launch_bounds__(224) k_agg() {
    int d = blockIdx.x;
    int c = threadIdx.x;
    int s0 = g_off[d], s1 = g_off[d+1];
    const float4* rep4 = (const float4*)g_rep;
    float4 acc = make_float4(0.f,0.f,0.f,0.f);
    int i = s0;
    for (; i + 3 < s1; i += 4) {
        int sa = g_esrc[i], sb = g_esrc[i+1], sc = g_esrc[i+2], sd = g_esrc[i+3];
        float4 va = rep4[(size_t)sa*224 + c];
        float4 vb = rep4[(size_t)sb*224 + c];
        float4 vc = rep4[(size_t)sc*224 + c];
        float4 vd = rep4[(size_t)sd*224 + c];
        acc.x += (va.x+vb.x) + (vc.x+vd.x);
        acc.y += (va.y+vb.y) + (vc.y+vd.y);
        acc.z += (va.z+vb.z) + (vc.z+vd.z);
        acc.w += (va.w+vb.w) + (vc.w+vd.w);
    }
    for (; i < s1; i++) {
        int s = g_esrc[i];
        float4 v = rep4[(size_t)s*224 + c];
        acc.x += v.x; acc.y += v.y; acc.z += v.z; acc.w += v.w;
    }
    ((float4*)g_agg)[(size_t)d*224 + c] = acc;
}

__global__ void __launch_bounds__(256) k_hgat(const float* __restrict__ gatW) {
    __shared__ float ar[8][896];
    int n0 = blockIdx.x * 8;
    int tid = threadIdx.x;
    for (int idx = tid; idx < 8*896; idx += 256)
        ar[idx/896][idx%896] = g_agg[(size_t)(n0 + idx/896)*896 + (idx%896)];
    __syncthreads();
    int o = tid & 31, i = tid >> 5;
    float acc = 0.f;
    for (int k = 0; k < 896; k++) acc += ar[i][k] * gatW[k*32 + o];
    g_hgat[(size_t)(n0+i)*32 + o] = acc;
}

__global__ void k_attn(const float* __restrict__ attS, const float* __restrict__ attD) {
    int n = blockIdx.x*256 + threadIdx.x;
    if (n >= NN) return;
    float s0=0.f,s1=0.f,d0=0.f,d1=0.f;
#pragma unroll
    for (int c = 0; c < 16; c++) {
        float v0 = g_hgat[(size_t)n*32+c], v1 = g_hgat[(size_t)n*32+16+c];
        s0 += v0*attS[c];  s1 += v1*attS[16+c];
        d0 += v0*attD[c];  d1 += v1*attD[16+c];
    }
    g_asrc[2*n]=s0; g_asrc[2*n+1]=s1; g_adst[2*n]=d0; g_adst[2*n+1]=d1;
}

__device__ __forceinline__ float lrelu(float x){ return x > 0.f ? x : 0.2f*x; }

__global__ void __launch_bounds__(256) k_gat(const float* __restrict__ gatBias) {
    int d = blockIdx.x*8 + (threadIdx.x >> 5);
    int l = threadIdx.x & 31;
    int s0 = g_off[d], s1 = g_off[d+1];
    float ad0 = g_adst[2*d], ad1 = g_adst[2*d+1];
    float es0 = lrelu(g_asrc[2*d]   + ad0);
    float es1 = lrelu(g_asrc[2*d+1] + ad1);
    float m0 = (l==0) ? es0 : -INFINITY;
    float m1 = (l==0) ? es1 : -INFINITY;
    for (int i = s0 + l; i < s1; i += 32) {
        int s = g_esrc[i];
        m0 = fmaxf(m0, lrelu(g_asrc[2*s]   + ad0));
        m1 = fmaxf(m1, lrelu(g_asrc[2*s+1] + ad1));
    }
#pragma unroll
    for (int o = 16; o; o >>= 1) {
        m0 = fmaxf(m0, __shfl_xor_sync(0xffffffffu, m0, o));
        m1 = fmaxf(m1, __shfl_xor_sync(0xffffffffu, m1, o));
    }
    float z0 = (l==0) ? expf(es0 - m0) : 0.f;
    float z1 = (l==0) ? expf(es1 - m1) : 0.f;
    for (int i = s0 + l; i < s1; i += 32) {
        int s = g_esrc[i];
        z0 += expf(lrelu(g_asrc[2*s]   + ad0) - m0);
        z1 += expf(lrelu(g_asrc[2*s+1] + ad1) - m1);
    }
#pragma unroll
    for (int o = 16; o; o >>= 1) {
        z0 += __shfl_xor_sync(0xffffffffu, z0, o);
        z1 += __shfl_xor_sync(0xffffffffu, z1, o);
    }
    int hh = l >> 4;
    float mh  = hh ? m1 : m0;
    float inv = 1.f / (hh ? z1 : z0);
    float adh = hh ? ad1 : ad0;
    float acc = 0.f;
    for (int i = s0; i < s1; i++) {
        int s = g_esrc[i];
        float al = expf(lrelu(g_asrc[2*s+hh] + adh) - mh) * inv;
        acc += al * g_hgat[(size_t)s*32 + l];
    }
    {
        float al = expf(lrelu(g_asrc[2*d+hh] + adh) - mh) * inv;
        acc += al * g_hgat[(size_t)d*32 + l];
    }
    g_gatout[(size_t)d*32 + l] = acc + gatBias[l];
}

__global__ void k_mlp(const float* __restrict__ mlpW, const float* __restrict__ mlpb) {
    int idx = blockIdx.x*256 + threadIdx.x;
    if (idx >= NN*16) return;
    int n = idx >> 4, c = idx & 15;
    float acc = mlpb[c];
#pragma unroll
    for (int o = 0; o < 32; o++) {
        float v = g_gatout[(size_t)n*32+o];
        v = v > 0.f ? v : (expf(v) - 1.f);
        acc += v * mlpW[o*16 + c];
    }
    g_gv[idx] = acc;
}

__global__ void k_out2() {
    int idx = blockIdx.x*256 + threadIdx.x;
    if (idx >= NN*16) return;
    int d = idx >> 4, c = idx & 15;
    int s0 = g_off[d], s1 = g_off[d+1];
    float acc = 0.f;
    for (int i = s0; i < s1; i++) acc += g_gv[(size_t)g_esrc[i]*16 + c];
    g_o2[idx] = acc;
}

__global__ void k_lsm(float* __restrict__ out) {
    int n = blockIdx.x*256 + threadIdx.x;
    if (n >= NN) return;
    float v[16]; float m = -INFINITY;
#pragma unroll
    for (int c = 0; c < 16; c++) { v[c] = g_o2[(size_t)n*16+c]; m = fmaxf(m, v[c]); }
    float z = 0.f;
#pragma unroll
    for (int c = 0; c < 16; c++) z += expf(v[c]-m);
    float lse = m + logf(z);
#pragma unroll
    for (int c = 0; c < 16; c++) out[(size_t)n*16+c] = v[c]-lse;
}

// ---------------- host ----------------
typedef CUresult (CUDAAPI *PFN_tmap)(CUtensorMap*, CUtensorMapDataType, cuuint32_t, void*,
    const cuuint64_t*, const cuuint64_t*, const cuuint32_t*, const cuuint32_t*,
    CUtensorMapInterleave, CUtensorMapSwizzle, CUtensorMapL2promotion, CUtensorMapFloatOOBfill);
static PFN_tmap g_enc = nullptr;

static void makeMapBox(CUtensorMap* m, void* ptr, unsigned long long d1, unsigned box1) {
    cuuint64_t dims[2] = {(cuuint64_t)NN, (cuuint64_t)d1};
    cuuint64_t strides[1] = {(cuuint64_t)NN * 2};
    cuuint32_t box[2] = {64u, (cuuint32_t)box1};
    cuuint32_t es[2] = {1u, 1u};
    g_enc(m, CU_TENSOR_MAP_DATA_TYPE_BFLOAT16, 2, ptr, dims, strides, box, es,
          CU_TENSOR_MAP_INTERLEAVE_NONE, CU_TENSOR_MAP_SWIZZLE_128B,
          CU_TENSOR_MAP_L2_PROMOTION_L2_128B, CU_TENSOR_MAP_FLOAT_OOB_FILL_NONE);
}

extern "C" void kernel_launch(void* const* d_in, const int* in_sizes, int n_in,
                              void* d_out, int out_size) {
    const float* x    = (const float*)d_in[0];
    const void*  ei   = d_in[1];
    const float* lamb = (const float*)d_in[2];
    const float* V    = (const float*)d_in[3];
    const float* W1   = (const float*)d_in[4];
    const float* b1   = (const float*)d_in[5];
    const float* gatW = (const float*)d_in[6];
    const float* attS = (const float*)d_in[7];
    const float* attD = (const float*)d_in[8];
    const float* gatB = (const float*)d_in[9];
    const float* mlpW = (const float*)d_in[10];
    const float* mlpB = (const float*)d_in[11];
    float* out = (float*)d_out;

    if (!g_enc) {
        cudaDriverEntryPointQueryResult st;
        cudaGetDriverEntryPointByVersion("cuTensorMapEncodeTiled", (void**)&g_enc, 12000,
                                         cudaEnableDefault, &st);
    }

    void *pVh, *pVl, *pVTh, *pVTl;
    void *phTh, *phTl, *pS1h, *pS1l, *pX2h, *pX2l, *pS2h, *pS2l, *pX3h, *pX3l, *pS3h, *pS3l;
    float *h_, *C1_, *Y_, *C2_, *Z_, *C3_, *Wo_;
    void *pDeg, *pOff, *pCur;
    cudaGetSymbolAddress(&pVh,  g_Vhi);  cudaGetSymbolAddress(&pVl,  g_Vlo);
    cudaGetSymbolAddress(&pVTh, g_VThi); cudaGetSymbolAddress(&pVTl, g_VTlo);
    cudaGetSymbolAddress(&phTh, g_hTh);  cudaGetSymbolAddress(&phTl, g_hTl);
    cudaGetSymbolAddress(&pS1h, g_S1Th); cudaGetSymbolAddress(&pS1l, g_S1Tl);
    cudaGetSymbolAddress(&pX2h, g_X2Th); cudaGetSymbolAddress(&pX2l, g_X2Tl);
    cudaGetSymbolAddress(&pS2h, g_S2Th); cudaGetSymbolAddress(&pS2l, g_S2Tl);
    cudaGetSymbolAddress(&pX3h, g_X3Th); cudaGetSymbolAddress(&pX3l, g_X3Tl);
    cudaGetSymbolAddress(&pS3h, g_S3Th); cudaGetSymbolAddress(&pS3l, g_S3Tl);
    cudaGetSymbolAddress((void**)&h_,  g_h);
    cudaGetSymbolAddress((void**)&C1_, g_C1);
    cudaGetSymbolAddress((void**)&Y_,  g_Y);
    cudaGetSymbolAddress((void**)&C2_, g_C2);
    cudaGetSymbolAddress((void**)&Z_,  g_Z);
    cudaGetSymbolAddress((void**)&C3_, g_C3);
    cudaGetSymbolAddress((void**)&Wo_, g_Wo);
    cudaGetSymbolAddress(&pDeg, g_deg);
    cudaGetSymbolAddress(&pOff, g_off);
    cudaGetSymbolAddress(&pCur, g_cur);

    cudaFuncSetAttribute(gemm_mma, cudaFuncAttributeMaxDynamicSharedMemorySize, SMEM_SZ);

    CUtensorMap mVh, mVl, mVTh, mVTl;
    makeMapBox(&mVh,  pVh,  NN, 128);
    makeMapBox(&mVl,  pVl,  NN, 128);
    makeMapBox(&mVTh, pVTh, NN, 128);
    makeMapBox(&mVTl, pVTl, NN, 128);

    const dim3 tb(32,8);
    auto run = [&](const CUtensorMap& Ah, const CUtensorMap& Al,
                   void* Bh, void* Bl, float* C, int NC) {
        CUtensorMap tBh, tBl;
        makeMapBox(&tBh, Bh, NC, 128);
        makeMapBox(&tBl, Bl, NC, 128);
        gemm_mma<<<dim3(NC/128, 79), 256, SMEM_SZ>>>(Ah, Al, tBh, tBl, C, NC);
    };

    // ===== front-end + GEMM chain (gemm G1 at launch slot 4) =====
    k_xw1<<<NN/8,128>>>(x, W1, b1);                                               // 1
    k_tsplit<0><<<dim3(313,4),tb>>>(h_, 128, 0, (__nv_bfloat16*)phTh, (__nv_bfloat16*)phTl, 128, 0); // 2
    k_splitAll<<<dim3(313,313),dim3(32,8)>>>(V);                                  // 3
    run(mVTh, mVTl, phTh, phTl, C1_, 128);                                        // 4 = gemm G1
    k_filters<<<CDIV(NN,256),256>>>(lamb);                                        // 5
    for (int t = 0; t < 3; t++)
        k_tsplit<2><<<dim3(313,4),tb>>>(C1_, 128, 0,
            (__nv_bfloat16*)pS1h + (size_t)t*128*NN, (__nv_bfloat16*)pS1l + (size_t)t*128*NN, 128, t);
    run(mVh, mVl, pS1h, pS1l, Y_, 384);
    k_tsplit<1><<<dim3(313,8),tb>>>(Y_, 384, 128, (__nv_bfloat16*)pX2h, (__nv_bfloat16*)pX2l, 256, 0);
    run(mVTh, mVTl, pX2h, pX2l, C2_, 256);
    for (int t = 0; t < 3; t++)
        k_tsplit<2><<<dim3(313,8),tb>>>(C2_, 256, 0,
            (__nv_bfloat16*)pS2h + (size_t)t*256*NN, (__nv_bfloat16*)pS2l + (size_t)t*256*NN, 256, t);
    run(mVh, mVl, pS2h, pS2l, Z_, 768);
    k_tsplit<3><<<dim3(313,16),tb>>>(Z_, 768, 0, (__nv_bfloat16*)pX3h, (__nv_bfloat16*)pX3l, 512, 0);
    run(mVTh, mVTl, pX3h, pX3l, C3_, 512);
    k_tsplit<2><<<dim3(313,16),tb>>>(C3_, 512, 0, (__nv_bfloat16*)pS3h, (__nv_bfloat16*)pS3l, 512, 0);
    run(mVh, mVl, pS3h, pS3l, Wo_, 512);
    k_rep<<<NN,256>>>();

    // ===== edge CSR (only k_agg onwards depends on it) =====
    k_detect<<<1,256>>>((const unsigned int*)ei);
    k_conv<<<CDIV(EE,256),256>>>(ei);
    cudaMemsetAsync(pDeg, 0, NN*sizeof(int));
    k_deg<<<CDIV(EE,256),256>>>();
    k_scan<<<1,1024>>>();
    cudaMemcpyAsync(pCur, pOff, NN*sizeof(int), cudaMemcpyDeviceToDevice);
    k_scatter<<<CDIV(EE,256),256>>>();

    // ===== graph aggregation + GAT + MLP + final agg + log_softmax =====
    k_agg<<<NN,224>>>();
    k_hgat<<<NN/8,256>>>(gatW);
    k_attn<<<CDIV(NN,256),256>>>(attS, attD);
    k_gat<<<NN/8,256>>>(gatB);
    k_mlp<<<CDIV(NN*16,256),256>>>(mlpW, mlpB);
    k_out2<<<CDIV(NN*16,256),256>>>();
    k_lsm<<<CDIV(NN,256),256>>>(out);
    (void)in_sizes; (void)n_in; (void)out_size;
}

// round 15
// speedup vs baseline: 1.7881x; 1.7881x over previous
#include <cuda_runtime.h>
#include <cuda.h>
#include <cuda_bf16.h>
#include <math.h>
#include <stdint.h>

#define NN 10000
#define EE 320000
#define PI_F 3.14159265358979323846f
#define CDIV(a,b) (((a)+(b)-1)/(b))

// GEMM config: 2-stage TMA pipeline, 128x64 CTA tile, K-chunk 64 (bf16), 2 CTAs/SM
#define GK_NIT 157
#define NSTG 2
#define STG_BYTES 49152
#define OFF_AH 0
#define OFF_AL 16384
#define OFF_BH 32768
#define OFF_BL 40960
#define SM_MB  98304
#define SMEM_SZ 98368

// ---------------- scratch ----------------
__device__ __nv_bfloat16 g_Vhi [100000000];
__device__ __nv_bfloat16 g_Vlo [100000000];
__device__ __nv_bfloat16 g_VThi[100000000];
__device__ __nv_bfloat16 g_VTlo[100000000];
__device__ __nv_bfloat16 g_hTh [128*NN],  g_hTl [128*NN];
__device__ __nv_bfloat16 g_S1Th[384*NN],  g_S1Tl[384*NN];
__device__ __nv_bfloat16 g_X2Th[256*NN],  g_X2Tl[256*NN];
__device__ __nv_bfloat16 g_S2Th[768*NN],  g_S2Tl[768*NN];
__device__ __nv_bfloat16 g_X3Th[512*NN],  g_X3Tl[512*NN];
__device__ __nv_bfloat16 g_S3Th[512*NN],  g_S3Tl[512*NN];

__device__ float g_h [NN*128];
__device__ float g_C1[NN*128];
__device__ float g_Y [NN*384];
__device__ float g_C2[NN*256];
__device__ float g_Z [NN*768];
__device__ float g_C3[NN*512];
__device__ float g_Wo[NN*512];
__device__ float g_rep[NN*896];
__device__ float g_agg[NN*896];
__device__ float g_filt[3*NN];
__device__ int   g_src[EE];
__device__ int   g_dst[EE];
__device__ int   g_is64;
__device__ int   g_deg[NN];
__device__ int   g_off[NN+1];
__device__ int   g_cur[NN];
__device__ int   g_esrc[EE];
__device__ float g_hgat[NN*32];
__device__ float g_asrc[NN*2];
__device__ float g_adst[NN*2];
__device__ float g_gatout[NN*32];
__device__ float g_gv[NN*16];
__device__ float g_o2[NN*16];

// ---------------- PTX helpers (base-target features only) ----------------
__device__ __forceinline__ uint32_t su32(const void* p) {
    uint32_t a;
    asm("{ .reg .u64 t; cvta.to.shared.u64 t, %1; cvt.u32.u64 %0, t; }" : "=r"(a) : "l"(p));
    return a;
}
#define MBAR_INIT(a, cnt) \
    asm volatile("mbarrier.init.shared.b64 [%0], %1;" :: "r"(a), "r"((uint32_t)(cnt)) : "memory")
#define MBAR_EXPECT_TX(a, b) \
    asm volatile("mbarrier.arrive.expect_tx.shared.b64 _, [%0], %1;" :: "r"(a), "r"((uint32_t)(b)) : "memory")
#define MBAR_WAIT(a, ph) do { \
    uint32_t _m = (a); uint32_t _p = (ph); uint32_t _d; \
    asm volatile("{\n\t.reg .pred p;\n\t" \
        "mbarrier.try_wait.parity.shared.b64 p, [%1], %2;\n\t" \
        "selp.b32 %0, 1, 0, p;\n\t}" : "=r"(_d) : "r"(_m), "r"(_p) : "memory"); \
    if (!_d) { \
        asm volatile("{\n\t.reg .pred P1;\n\t" \
            "WL_%=:\n\t" \
            "mbarrier.try_wait.parity.shared.b64 P1, [%0], %1;\n\t" \
            "@P1 bra.uni WD_%=;\n\t" \
            "bra.uni WL_%=;\n\t" \
            "WD_%=:\n\t}" :: "r"(_m), "r"(_p) : "memory"); \
    } } while (0)

__device__ __forceinline__ void tma2d(uint32_t sa, const CUtensorMap* tm, int x, int y, uint32_t mb) {
    asm volatile(
        "cp.async.bulk.tensor.2d.shared::cta.global.tile.mbarrier::complete_tx::bytes "
        "[%0], [%1, {%2, %3}], [%4];"
        :: "r"(sa), "l"(tm), "r"(x), "r"(y), "r"(mb) : "memory");
}
__device__ __forceinline__ void ldm_x4(uint32_t* r, uint32_t addr) {
    asm volatile("ldmatrix.sync.aligned.m8n8.x4.shared.b16 {%0,%1,%2,%3}, [%4];"
        : "=r"(r[0]), "=r"(r[1]), "=r"(r[2]), "=r"(r[3]) : "r"(addr));
}
__device__ __forceinline__ void mma16816(float* d, const uint32_t* a, uint32_t b0, uint32_t b1) {
    asm volatile("mma.sync.aligned.m16n8k16.row.col.f32.bf16.bf16.f32 "
        "{%0,%1,%2,%3}, {%4,%5,%6,%7}, {%8,%9}, {%0,%1,%2,%3};"
        : "+f"(d[0]), "+f"(d[1]), "+f"(d[2]), "+f"(d[3])
        : "r"(a[0]), "r"(a[1]), "r"(a[2]), "r"(a[3]), "r"(b0), "r"(b1));
}
#define SWZ(o) ((o) ^ (((o) >> 3) & 0x70))

// ---------------- HMMA GEMM: C[10000,NC] = A(row-major,K=10000) @ B([NC][K] k-major)^T ----------------
// CTA tile 128(M) x 64(N); 2 CTAs/SM. grid.x = bn tiles (fast), grid.y = bm tiles.
__global__ void __launch_bounds__(256, 2) gemm_mma(
    const __grid_constant__ CUtensorMap tmAh,
    const __grid_constant__ CUtensorMap tmAl,
    const __grid_constant__ CUtensorMap tmBh,
    const __grid_constant__ CUtensorMap tmBl,
    float* __restrict__ C, int NC)
{
    extern __shared__ char smem[];
    const uint32_t sb = su32(smem);
    const int tid = threadIdx.x, wid = tid >> 5, lane = tid & 31;
    const int bn = blockIdx.x * 64;
    const int bm = blockIdx.y * 128;
    const int warp_m = (wid & 3) * 32;
    const int warp_n = (wid >> 2) * 32;
    const int lrow  = lane & 15;
    const int lcolb = (lane >> 4) << 4;

    if (tid == 0) {
        #pragma unroll
        for (int s = 0; s < NSTG; s++) MBAR_INIT(sb + SM_MB + s*8, 1);
        asm volatile("fence.proxy.async.shared::cta;" ::: "memory");
    }
    __syncthreads();

    if (tid == 0) {
        #pragma unroll
        for (int p = 0; p < NSTG; p++) {
            uint32_t base = sb + p * STG_BYTES;
            MBAR_EXPECT_TX(sb + SM_MB + p*8, STG_BYTES);
            tma2d(base + OFF_AH, &tmAh, p*64, bm, sb + SM_MB + p*8);
            tma2d(base + OFF_AL, &tmAl, p*64, bm, sb + SM_MB + p*8);
            tma2d(base + OFF_BH, &tmBh, p*64, bn, sb + SM_MB + p*8);
            tma2d(base + OFF_BL, &tmBl, p*64, bn, sb + SM_MB + p*8);
        }
    }

    float acc[2][4][4];
    #pragma unroll
    for (int mt = 0; mt < 2; mt++)
        #pragma unroll
        for (int nt = 0; nt < 4; nt++)
            #pragma unroll
            for (int r = 0; r < 4; r++) acc[mt][nt][r] = 0.f;

    int b = 0;
    for (int it = 0; it < GK_NIT; it++) {
        MBAR_WAIT(sb + SM_MB + b*8, (it >> 1) & 1);
        const uint32_t base = sb + b * STG_BYTES;
        #pragma unroll
        for (int k16 = 0; k16 < 4; k16++) {
            const int kb = k16 * 32;
            uint32_t ah[2][4], al[2][4];
            #pragma unroll
            for (int mt = 0; mt < 2; mt++) {
                uint32_t sw = SWZ((uint32_t)((warp_m + mt*16 + lrow) * 128 + kb + lcolb));
                ldm_x4(ah[mt], base + OFF_AH + sw);
                ldm_x4(al[mt], base + OFF_AL + sw);
            }
            #pragma unroll
            for (int j = 0; j < 2; j++) {
                uint32_t sw = SWZ((uint32_t)((warp_n + j*16 + lrow) * 128 + kb + lcolb));
                uint32_t bh[4], bl[4];
                ldm_x4(bh, base + OFF_BH + sw);
                ldm_x4(bl, base + OFF_BL + sw);
                #pragma unroll
                for (int mt = 0; mt < 2; mt++) {
                    mma16816(acc[mt][2*j],   ah[mt], bh[0], bh[2]);
                    mma16816(acc[mt][2*j+1], ah[mt], bh[1], bh[3]);
                    mma16816(acc[mt][2*j],   ah[mt], bl[0], bl[2]);
                    mma16816(acc[mt][2*j+1], ah[mt], bl[1], bl[3]);
                    mma16816(acc[mt][2*j],   al[mt], bh[0], bh[2]);
                    mma16816(acc[mt][2*j+1], al[mt], bh[1], bh[3]);
                }
            }
        }
        __syncthreads();
        if (tid == 0 && it + NSTG < GK_NIT) {
            MBAR_EXPECT_TX(sb + SM_MB + b*8, STG_BYTES);
            const int k0 = (it + NSTG) * 64;
            tma2d(base + OFF_AH, &tmAh, k0, bm, sb + SM_MB + b*8);
            tma2d(base + OFF_AL, &tmAl, k0, bm, sb + SM_MB + b*8);
            tma2d(base + OFF_BH, &tmBh, k0, bn, sb + SM_MB + b*8);
            tma2d(base + OFF_BL, &tmBl, k0, bn, sb + SM_MB + b*8);
        }
        b ^= 1;
    }

    // epilogue
    #pragma unroll
    for (int mt = 0; mt < 2; mt++) {
        #pragma unroll
        for (int nt = 0; nt < 4; nt++) {
            int row0 = bm + warp_m + mt*16 + (lane >> 2);
            int col  = bn + warp_n + nt*8 + (lane & 3)*2;
            if (row0 < NN) {
                float2 v; v.x = acc[mt][nt][0]; v.y = acc[mt][nt][1];
                *(float2*)&C[(size_t)row0 * NC + col] = v;
            }
            if (row0 + 8 < NN) {
                float2 v; v.x = acc[mt][nt][2]; v.y = acc[mt][nt][3];
                *(float2*)&C[(size_t)(row0 + 8) * NC + col] = v;
            }
        }
    }
}

// ---------------- prep: fused split + transpose-split of V (read V once) ----------------
__global__ void k_splitAll(const float* __restrict__ V) {
    __shared__ float t[32][33];
    int i0 = blockIdx.x*32, j0 = blockIdx.y*32;
    int x = threadIdx.x, y0 = threadIdx.y;
    #pragma unroll
    for (int yy = 0; yy < 32; yy += 8) {
        int i = i0 + y0 + yy, j = j0 + x;
        float v = 0.f;
        if (i < NN && j < NN) {
            v = V[(size_t)i*NN + j];
            __nv_bfloat16 h = __float2bfloat16(v);
            g_Vhi[(size_t)i*NN + j] = h;
            g_Vlo[(size_t)i*NN + j] = __float2bfloat16(v - __bfloat162float(h));
        }
        t[y0+yy][x] = v;
    }
    __syncthreads();
    #pragma unroll
    for (int yy = 0; yy < 32; yy += 8) {
        int j = j0 + y0 + yy, i = i0 + x;
        if (j < NN && i < NN) {
            float v = t[x][y0+yy];
            __nv_bfloat16 h = __float2bfloat16(v);
            g_VThi[(size_t)j*NN + i] = h;
            g_VTlo[(size_t)j*NN + i] = __float2bfloat16(v - __bfloat162float(h));
        }
    }
}

// MODE 0: copy, 1: abs, 2: scale by filt[filtIdx], 3: Z col remap + abs
template<int MODE>
__global__ void k_tsplit(const float* __restrict__ src, int srcW, int col0,
                         __nv_bfloat16* __restrict__ oh, __nv_bfloat16* __restrict__ ol,
                         int outRows, int filtIdx)
{
    __shared__ float t[32][33];
    int i0 = blockIdx.x*32;
    int j0 = blockIdx.y*32;
    int x = threadIdx.x, y0 = threadIdx.y;
    #pragma unroll
    for (int yy = 0; yy < 32; yy += 8) {
        int i = i0 + y0 + yy, j = j0 + x;
        float v = 0.f;
        if (i < NN && j < outRows) {
            int c;
            if (MODE == 3) { const int zo[4] = {256,512,384,640}; c = zo[j>>7] + (j&127); }
            else c = col0 + j;
            v = src[(size_t)i*srcW + c];
            if (MODE == 1 || MODE == 3) v = fabsf(v);
            if (MODE == 2) v *= g_filt[filtIdx*NN + i];
        }
        t[y0+yy][x] = v;
    }
    __syncthreads();
    #pragma unroll
    for (int yy = 0; yy < 32; yy += 8) {
        int j = j0 + y0 + yy, i = i0 + x;
        if (j < outRows && i < NN) {
            float v = t[x][y0+yy];
            __nv_bfloat16 h = __float2bfloat16(v);
            oh[(size_t)j*NN + i] = h;
            ol[(size_t)j*NN + i] = __float2bfloat16(v - __bfloat162float(h));
        }
    }
}

// ---------------- front-end / edges / graph stages ----------------
__global__ void k_detect(const unsigned int* __restrict__ w) {
    __shared__ unsigned acc_s;
    if (threadIdx.x == 0) acc_s = 0u;
    __syncthreads();
    unsigned a = 0u;
    for (int i = threadIdx.x; i < 4096; i += blockDim.x) a |= w[2*i + 1];
    atomicOr(&acc_s, a);
    __syncthreads();
    if (threadIdx.x == 0) g_is64 = (acc_s == 0u) ? 1 : 0;
}

__global__ void k_conv(const void* __restrict__ ei) {
    int e = blockIdx.x*256 + threadIdx.x;
    if (e >= EE) return;
    if (g_is64) {
        const long long* p = (const long long*)ei;
        g_src[e] = (int)p[e];  g_dst[e] = (int)p[EE + e];
    } else {
        const int* p = (const int*)ei;
        g_src[e] = p[e];  g_dst[e] = p[EE + e];
    }
}

__global__ void k_filters(const float* __restrict__ lamb) {
    int i = blockIdx.x*256 + threadIdx.x;
    if (i >= NN) return;
    float lam = lamb[i];
    float l0 = 8.f*lam; if (l0 == 0.f) l0 = 1e-7f;
    float y0 = 2.f*PI_F*l0;
    g_filt[i] = sinf(y0)/y0;
    float l1 = lam*0.25f; if (l1 == 0.f) l1 = 1e-8f;
    g_filt[NN+i]   = sinf(l1)/(PI_F*l1)*(1.f-cosf(l1));
    float l2 = lam*0.5f;  if (l2 == 0.f) l2 = 1e-8f;
    g_filt[2*NN+i] = sinf(l2)/(PI_F*l2)*(1.f-cosf(l2));
}

__global__ void k_xw1(const float* __restrict__ x, const float* __restrict__ W1, const float* __restrict__ b1) {
    __shared__ float xr[8][128];
    int n0 = blockIdx.x * 8;
    int c = threadIdx.x;
#pragma unroll
    for (int i = 0; i < 8; i++) xr[i][c] = x[(size_t)(n0+i)*128 + c];
    __syncthreads();
    float acc[8];
#pragma unroll
    for (int i = 0; i < 8; i++) acc[i] = b1[c];
    for (int k = 0; k < 128; k++) {
        float w = W1[k*128 + c];
#pragma unroll
        for (int i = 0; i < 8; i++) acc[i] += xr[i][k]*w;
    }
#pragma unroll
    for (int i = 0; i < 8; i++) g_h[(size_t)(n0+i)*128 + c] = acc[i];
}

__global__ void k_rep() {
    int i = blockIdx.x;
    for (int j = threadIdx.x; j < 896; j += blockDim.x) {
        float v;
        if (j < 128)      v = g_Y[(size_t)i*384 + j];
        else if (j < 384) v = g_Z[(size_t)i*768 + (j-128)];
        else              v = g_Wo[(size_t)i*512 + (j-384)];
        g_rep[(size_t)i*896 + j] = v;
    }
}

__global__ void k_deg() {
    int e = blockIdx.x*256 + threadIdx.x;
    if (e < EE) atomicAdd(&g_deg[g_dst[e]], 1);
}

__global__ void k_scan() {
    __shared__ int sh[1024];
    __shared__ int carry;
    int tid = threadIdx.x;
    if (tid == 0) carry = 0;
    __syncthreads();
    for (int base = 0; base < NN; base += 1024) {
        int idx = base + tid;
        int v = (idx < NN) ? g_deg[idx] : 0;
        sh[tid] = v;
        __syncthreads();
        for (int o = 1; o < 1024; o <<= 1) {
            int t = (tid >= o) ? sh[tid-o] : 0;
            __syncthreads();
            sh[tid] += t;
            __syncthreads();
        }
        if (idx < NN) g_off[idx] = carry + sh[tid] - v;
        __syncthreads();
        if (tid == 0) carry += sh[1023];
        __syncthreads();
    }
    if (tid == 0) g_off[NN] = carry;
}

__global__ void k_scatter() {
    int e = blockIdx.x*256 + threadIdx.x;
    if (e < EE) {
        int d = g_dst[e];
        int pos = atomicAdd(&g_cur[d], 1);
        g_esrc[pos] = g_src[e];
    }
}

__global__ void __launch_bounds__(224) k_agg() {
    int d = blockIdx.x;
    int c = threadIdx.x;
    int s0 = g_off[d], s1 = g_off[d+1];
    const float4* rep4 = (const float4*)g_rep;
    float4 acc = make_float4(0.f,0.f,0.f,0.f);
    int i = s0;
    for (; i + 3 < s1; i += 4) {
        int sa = g_esrc[i], sb = g_esrc[i+1], sc = g_esrc[i+2], sd = g_esrc[i+3];
        float4 va = rep4[(size_t)sa*224 + c];
        float4 vb = rep4[(size_t)sb*224 + c];
        float4 vc = rep4[(size_t)sc*224 + c];
        float4 vd = rep4[(size_t)sd*224 + c];
        acc.x += (va.x+vb.x) + (vc.x+vd.x);
        acc.y += (va.y+vb.y) + (vc.y+vd.y);
        acc.z += (va.z+vb.z) + (vc.z+vd.z);
        acc.w += (va.w+vb.w) + (vc.w+vd.w);
    }
    for (; i < s1; i++) {
        int s = g_esrc[i];
        float4 v = rep4[(size_t)s*224 + c];
        acc.x += v.x; acc.y += v.y; acc.z += v.z; acc.w += v.w;
    }
    ((float4*)g_agg)[(size_t)d*224 + c] = acc;
}

__global__ void __launch_bounds__(256) k_hgat(const float* __restrict__ gatW) {
    __shared__ float ar[8][896];
    int n0 = blockIdx.x * 8;
    int tid = threadIdx.x;
    for (int idx = tid; idx < 8*896; idx += 256)
        ar[idx/896][idx%896] = g_agg[(size_t)(n0 + idx/896)*896 + (idx%896)];
    __syncthreads();
    int o = tid & 31, i = tid >> 5;
    float acc = 0.f;
    for (int k = 0; k < 896; k++) acc += ar[i][k] * gatW[k*32 + o];
    g_hgat[(size_t)(n0+i)*32 + o] = acc;
}

__global__ void k_attn(const float* __restrict__ attS, const float* __restrict__ attD) {
    int n = blockIdx.x*256 + threadIdx.x;
    if (n >= NN) return;
    float s0=0.f,s1=0.f,d0=0.f,d1=0.f;
#pragma unroll
    for (int c = 0; c < 16; c++) {
        float v0 = g_hgat[(size_t)n*32+c], v1 = g_hgat[(size_t)n*32+16+c];
        s0 += v0*attS[c];  s1 += v1*attS[16+c];
        d0 += v0*attD[c];  d1 += v1*attD[16+c];
    }
    g_asrc[2*n]=s0; g_asrc[2*n+1]=s1; g_adst[2*n]=d0; g_adst[2*n+1]=d1;
}

__device__ __forceinline__ float lrelu(float x){ return x > 0.f ? x : 0.2f*x; }

__global__ void __launch_bounds__(256) k_gat(const float* __restrict__ gatBias) {
    int d = blockIdx.x*8 + (threadIdx.x >> 5);
    int l = threadIdx.x & 31;
    int s0 = g_off[d], s1 = g_off[d+1];
    float ad0 = g_adst[2*d], ad1 = g_adst[2*d+1];
    float es0 = lrelu(g_asrc[2*d]   + ad0);
    float es1 = lrelu(g_asrc[2*d+1] + ad1);
    float m0 = (l==0) ? es0 : -INFINITY;
    float m1 = (l==0) ? es1 : -INFINITY;
    for (int i = s0 + l; i < s1; i += 32) {
        int s = g_esrc[i];
        m0 = fmaxf(m0, lrelu(g_asrc[2*s]   + ad0));
        m1 = fmaxf(m1, lrelu(g_asrc[2*s+1] + ad1));
    }
#pragma unroll
    for (int o = 16; o; o >>= 1) {
        m0 = fmaxf(m0, __shfl_xor_sync(0xffffffffu, m0, o));
        m1 = fmaxf(m1, __shfl_xor_sync(0xffffffffu, m1, o));
    }
    float z0 = (l==0) ? expf(es0 - m0) : 0.f;
    float z1 = (l==0) ? expf(es1 - m1) : 0.f;
    for (int i = s0 + l; i < s1; i += 32) {
        int s = g_esrc[i];
        z0 += expf(lrelu(g_asrc[2*s]   + ad0) - m0);
        z1 += expf(lrelu(g_asrc[2*s+1] + ad1) - m1);
    }
#pragma unroll
    for (int o = 16; o; o >>= 1) {
        z0 += __shfl_xor_sync(0xffffffffu, z0, o);
        z1 += __shfl_xor_sync(0xffffffffu, z1, o);
    }
    int hh = l >> 4;
    float mh  = hh ? m1 : m0;
    float inv = 1.f / (hh ? z1 : z0);
    float adh = hh ? ad1 : ad0;
    float acc = 0.f;
    for (int i = s0; i < s1; i++) {
        int s = g_esrc[i];
        float al = expf(lrelu(g_asrc[2*s+hh] + adh) - mh) * inv;
        acc += al * g_hgat[(size_t)s*32 + l];
    }
    {
        float al = expf(lrelu(g_asrc[2*d+hh] + adh) - mh) * inv;
        acc += al * g_hgat[(size_t)d*32 + l];
    }
    g_gatout[(size_t)d*32 + l] = acc + gatBias[l];
}

__global__ void k_mlp(const float* __restrict__ mlpW, const float* __restrict__ mlpb) {
    int idx = blockIdx.x*256 + threadIdx.x;
    if (idx >= NN*16) return;
    int n = idx >> 4, c = idx & 15;
    float acc = mlpb[c];
#pragma unroll
    for (int o = 0; o < 32; o++) {
        float v = g_gatout[(size_t)n*32+o];
        v = v > 0.f ? v : (expf(v) - 1.f);
        acc += v * mlpW[o*16 + c];
    }
    g_gv[idx] = acc;
}

__global__ void k_out2() {
    int idx = blockIdx.x*256 + threadIdx.x;
    if (idx >= NN*16) return;
    int d = idx >> 4, c = idx & 15;
    int s0 = g_off[d], s1 = g_off[d+1];
    float acc = 0.f;
    for (int i = s0; i < s1; i++) acc += g_gv[(size_t)g_esrc[i]*16 + c];
    g_o2[idx] = acc;
}

__global__ void k_lsm(float* __restrict__ out) {
    int n = blockIdx.x*256 + threadIdx.x;
    if (n >= NN) return;
    float v[16]; float m = -INFINITY;
#pragma unroll
    for (int c = 0; c < 16; c++) { v[c] = g_o2[(size_t)n*16+c]; m = fmaxf(m, v[c]); }
    float z = 0.f;
#pragma unroll
    for (int c = 0; c < 16; c++) z += expf(v[c]-m);
    float lse = m + logf(z);
#pragma unroll
    for (int c = 0; c < 16; c++) out[(size_t)n*16+c] = v[c]-lse;
}

// ---------------- host ----------------
typedef CUresult (CUDAAPI *PFN_tmap)(CUtensorMap*, CUtensorMapDataType, cuuint32_t, void*,
    const cuuint64_t*, const cuuint64_t*, const cuuint32_t*, const cuuint32_t*,
    CUtensorMapInterleave, CUtensorMapSwizzle, CUtensorMapL2promotion, CUtensorMapFloatOOBfill);
static PFN_tmap g_enc = nullptr;

static void makeMapBox(CUtensorMap* m, void* ptr, unsigned long long d1, unsigned box1) {
    cuuint64_t dims[2] = {(cuuint64_t)NN, (cuuint64_t)d1};
    cuuint64_t strides[1] = {(cuuint64_t)NN * 2};
    cuuint32_t box[2] = {64u, (cuuint32_t)box1};
    cuuint32_t es[2] = {1u, 1u};
    g_enc(m, CU_TENSOR_MAP_DATA_TYPE_BFLOAT16, 2, ptr, dims, strides, box, es,
          CU_TENSOR_MAP_INTERLEAVE_NONE, CU_TENSOR_MAP_SWIZZLE_128B,
          CU_TENSOR_MAP_L2_PROMOTION_L2_128B, CU_TENSOR_MAP_FLOAT_OOB_FILL_NONE);
}

extern "C" void kernel_launch(void* const* d_in, const int* in_sizes, int n_in,
                              void* d_out, int out_size) {
    const float* x    = (const float*)d_in[0];
    const void*  ei   = d_in[1];
    const float* lamb = (const float*)d_in[2];
    const float* V    = (const float*)d_in[3];
    const float* W1   = (const float*)d_in[4];
    const float* b1   = (const float*)d_in[5];
    const float* gatW = (const float*)d_in[6];
    const float* attS = (const float*)d_in[7];
    const float* attD = (const float*)d_in[8];
    const float* gatB = (const float*)d_in[9];
    const float* mlpW = (const float*)d_in[10];
    const float* mlpB = (const float*)d_in[11];
    float* out = (float*)d_out;

    if (!g_enc) {
        cudaDriverEntryPointQueryResult st;
        cudaGetDriverEntryPointByVersion("cuTensorMapEncodeTiled", (void**)&g_enc, 12000,
                                         cudaEnableDefault, &st);
    }

    void *pVh, *pVl, *pVTh, *pVTl;
    void *phTh, *phTl, *pS1h, *pS1l, *pX2h, *pX2l, *pS2h, *pS2l, *pX3h, *pX3l, *pS3h, *pS3l;
    float *h_, *C1_, *Y_, *C2_, *Z_, *C3_, *Wo_;
    void *pDeg, *pOff, *pCur;
    cudaGetSymbolAddress(&pVh,  g_Vhi);  cudaGetSymbolAddress(&pVl,  g_Vlo);
    cudaGetSymbolAddress(&pVTh, g_VThi); cudaGetSymbolAddress(&pVTl, g_VTlo);
    cudaGetSymbolAddress(&phTh, g_hTh);  cudaGetSymbolAddress(&phTl, g_hTl);
    cudaGetSymbolAddress(&pS1h, g_S1Th); cudaGetSymbolAddress(&pS1l, g_S1Tl);
    cudaGetSymbolAddress(&pX2h, g_X2Th); cudaGetSymbolAddress(&pX2l, g_X2Tl);
    cudaGetSymbolAddress(&pS2h, g_S2Th); cudaGetSymbolAddress(&pS2l, g_S2Tl);
    cudaGetSymbolAddress(&pX3h, g_X3Th); cudaGetSymbolAddress(&pX3l, g_X3Tl);
    cudaGetSymbolAddress(&pS3h, g_S3Th); cudaGetSymbolAddress(&pS3l, g_S3Tl);
    cudaGetSymbolAddress((void**)&h_,  g_h);
    cudaGetSymbolAddress((void**)&C1_, g_C1);
    cudaGetSymbolAddress((void**)&Y_,  g_Y);
    cudaGetSymbolAddress((void**)&C2_, g_C2);
    cudaGetSymbolAddress((void**)&Z_,  g_Z);
    cudaGetSymbolAddress((void**)&C3_, g_C3);
    cudaGetSymbolAddress((void**)&Wo_, g_Wo);
    cudaGetSymbolAddress(&pDeg, g_deg);
    cudaGetSymbolAddress(&pOff, g_off);
    cudaGetSymbolAddress(&pCur, g_cur);

    cudaFuncSetAttribute(gemm_mma, cudaFuncAttributeMaxDynamicSharedMemorySize, SMEM_SZ);

    CUtensorMap mVh, mVl, mVTh, mVTl;
    makeMapBox(&mVh,  pVh,  NN, 128);
    makeMapBox(&mVl,  pVl,  NN, 128);
    makeMapBox(&mVTh, pVTh, NN, 128);
    makeMapBox(&mVTl, pVTl, NN, 128);

    const dim3 tb(32,8);
    auto run = [&](const CUtensorMap& Ah, const CUtensorMap& Al,
                   void* Bh, void* Bl, float* C, int NC) {
        CUtensorMap tBh, tBl;
        makeMapBox(&tBh, Bh, NC, 64);
        makeMapBox(&tBl, Bl, NC, 64);
        gemm_mma<<<dim3(NC/64, 79), 256, SMEM_SZ>>>(Ah, Al, tBh, tBl, C, NC);
    };

    // ===== front-end + GEMM chain (gemm G1 at launch slot 4 for ncu) =====
    k_xw1<<<NN/8,128>>>(x, W1, b1);                                               // 1
    k_tsplit<0><<<dim3(313,4),tb>>>(h_, 128, 0, (__nv_bfloat16*)phTh, (__nv_bfloat16*)phTl, 128, 0); // 2
    k_splitAll<<<dim3(313,313),dim3(32,8)>>>(V);                                  // 3
    run(mVTh, mVTl, phTh, phTl, C1_, 128);                                        // 4 = gemm G1
    k_filters<<<CDIV(NN,256),256>>>(lamb);                                        // 5
    for (int t = 0; t < 3; t++)
        k_tsplit<2><<<dim3(313,4),tb>>>(C1_, 128, 0,
            (__nv_bfloat16*)pS1h + (size_t)t*128*NN, (__nv_bfloat16*)pS1l + (size_t)t*128*NN, 128, t);
    run(mVh, mVl, pS1h, pS1l, Y_, 384);
    k_tsplit<1><<<dim3(313,8),tb>>>(Y_, 384, 128, (__nv_bfloat16*)pX2h, (__nv_bfloat16*)pX2l, 256, 0);
    run(mVTh, mVTl, pX2h, pX2l, C2_, 256);
    for (int t = 0; t < 3; t++)
        k_tsplit<2><<<dim3(313,8),tb>>>(C2_, 256, 0,
            (__nv_bfloat16*)pS2h + (size_t)t*256*NN, (__nv_bfloat16*)pS2l + (size_t)t*256*NN, 256, t);
    run(mVh, mVl, pS2h, pS2l, Z_, 768);
    k_tsplit<3><<<dim3(313,16),tb>>>(Z_, 768, 0, (__nv_bfloat16*)pX3h, (__nv_bfloat16*)pX3l, 512, 0);
    run(mVTh, mVTl, pX3h, pX3l, C3_, 512);
    k_tsplit<2><<<dim3(313,16),tb>>>(C3_, 512, 0, (__nv_bfloat16*)pS3h, (__nv_bfloat16*)pS3l, 512, 0);
    run(mVh, mVl, pS3h, pS3l, Wo_, 512);
    k_rep<<<NN,256>>>();

    // ===== edge CSR (only k_agg onwards depends on it) =====
    k_detect<<<1,256>>>((const unsigned int*)ei);
    k_conv<<<CDIV(EE,256),256>>>(ei);
    cudaMemsetAsync(pDeg, 0, NN*sizeof(int));
    k_deg<<<CDIV(EE,256),256>>>();
    k_scan<<<1,1024>>>();
    cudaMemcpyAsync(pCur, pOff, NN*sizeof(int), cudaMemcpyDeviceToDevice);
    k_scatter<<<CDIV(EE,256),256>>>();

    // ===== graph aggregation + GAT + MLP + final agg + log_softmax =====
    k_agg<<<NN,224>>>();
    k_hgat<<<NN/8,256>>>(gatW);
    k_attn<<<CDIV(NN,256),256>>>(attS, attD);
    k_gat<<<NN/8,256>>>(gatB);
    k_mlp<<<CDIV(NN*16,256),256>>>(mlpW, mlpB);
    k_out2<<<CDIV(NN*16,256),256>>>();
    k_lsm<<<CDIV(NN,256),256>>>(out);
    (void)in_sizes; (void)n_in; (void)out_size;
}